// round 1
// baseline (speedup 1.0000x reference)
#include <cuda_runtime.h>
#include <cuda_bf16.h>

#define HIDDEN 1024
#define EMBD   512
#define KAUG   1536
#define NOPS   8
#define BATCH  16384

// ---- device scratch (no runtime allocation allowed) ----
__device__ int   g_counts[NOPS];
__device__ int   g_bucket[NOPS][BATCH];
__device__ float g_H[(size_t)BATCH * HIDDEN];   // 64 MB intermediate, indexed by token

__global__ void zero_counts_kernel() {
    if (threadIdx.x < NOPS) g_counts[threadIdx.x] = 0;
}

__global__ void route_kernel(const int* __restrict__ ops) {
    int t = blockIdx.x * blockDim.x + threadIdx.x;
    if (t < BATCH) {
        int e = ops[t];
        int slot = atomicAdd(&g_counts[e], 1);
        g_bucket[e][slot] = t;
    }
}

// Grouped SGEMM: C[tok] = relu(gather(A)[tok] @ W[e] + b[e])
// L1: A = x (k<1024) + broadcast op_emb[e] (k>=1024), out = g_H
// L2: A = g_H, out = final output
// Tile: 128x128x16, 256 threads, 8x8/thread in split-4 subtiles (conflict-free LDS.128)
template<int KTOT, bool L1>
__global__ void __launch_bounds__(256, 2) grouped_gemm_kernel(
    const float* __restrict__ A0,
    const float* __restrict__ emb,
    const float* __restrict__ W,
    const float* __restrict__ bias,
    float* __restrict__ outp)
{
    const int e  = blockIdx.z;
    const int count = g_counts[e];
    const int m0 = blockIdx.y * 128;
    if (m0 >= count) return;
    const int n0 = blockIdx.x * 128;

    __shared__ float As[16][128];
    __shared__ float Bs[16][128];
    __shared__ int   sTok[128];

    const int tid = threadIdx.x;
    const int tx  = tid & 15;     // 16 col-groups
    const int ty  = tid >> 4;     // 16 row-groups

    if (tid < 128) {
        int idx = m0 + tid;
        sTok[tid] = g_bucket[e][idx < count ? idx : (count - 1)];
    }
    __syncthreads();

    const float* __restrict__ Asrc = L1 ? A0 : (const float*)g_H;
    const float* __restrict__ Wb   = W + (size_t)e * KTOT * HIDDEN;

    float acc[8][8];
    #pragma unroll
    for (int i = 0; i < 8; i++)
        #pragma unroll
        for (int j = 0; j < 8; j++) acc[i][j] = 0.0f;

    // per-thread A-load coords: 2 float4 per thread, 2 threads per row
    const int la_m  = tid >> 1;            // 0..127
    const int la_kc = (tid & 1) * 2;       // 0 or 2 (then +1 for second)

    for (int k0 = 0; k0 < KTOT; k0 += 16) {
        // ---- load A tile (gathered rows), transpose into As[k][m] ----
        #pragma unroll
        for (int r = 0; r < 2; r++) {
            int kc = la_kc + r;            // 0..3, chunk of 4 k's
            float4 v;
            if (L1 && k0 >= HIDDEN) {
                v = *(const float4*)&emb[e * EMBD + (k0 - HIDDEN) + kc * 4];
            } else {
                v = *(const float4*)&Asrc[(size_t)sTok[la_m] * HIDDEN + k0 + kc * 4];
            }
            As[kc * 4 + 0][la_m] = v.x;
            As[kc * 4 + 1][la_m] = v.y;
            As[kc * 4 + 2][la_m] = v.z;
            As[kc * 4 + 3][la_m] = v.w;
        }
        // ---- load B tile: Bs[k][n], n contiguous ----
        #pragma unroll
        for (int r = 0; r < 2; r++) {
            int idx = tid * 2 + r;         // 0..511
            int k   = idx >> 5;            // 0..15
            int nc  = idx & 31;            // float4 col
            *(float4*)&Bs[k][nc * 4] =
                *(const float4*)&Wb[(size_t)(k0 + k) * HIDDEN + n0 + nc * 4];
        }
        __syncthreads();

        #pragma unroll
        for (int k = 0; k < 16; k++) {
            float4 a0 = ((const float4*)As[k])[ty];
            float4 a1 = ((const float4*)As[k])[16 + ty];
            float4 b0 = ((const float4*)Bs[k])[tx];
            float4 b1 = ((const float4*)Bs[k])[16 + tx];
            float a[8] = {a0.x, a0.y, a0.z, a0.w, a1.x, a1.y, a1.z, a1.w};
            float b[8] = {b0.x, b0.y, b0.z, b0.w, b1.x, b1.y, b1.z, b1.w};
            #pragma unroll
            for (int i = 0; i < 8; i++)
                #pragma unroll
                for (int j = 0; j < 8; j++)
                    acc[i][j] = fmaf(a[i], b[j], acc[i][j]);
        }
        __syncthreads();
    }

    // ---- epilogue: +bias, relu, scatter rows by token ----
    float* __restrict__ outdst = L1 ? (float*)g_H : outp;

    float bb[8];
    #pragma unroll
    for (int jh = 0; jh < 2; jh++)
        #pragma unroll
        for (int j = 0; j < 4; j++)
            bb[jh * 4 + j] = bias[e * HIDDEN + n0 + jh * 64 + tx * 4 + j];

    #pragma unroll
    for (int ih = 0; ih < 2; ih++) {
        #pragma unroll
        for (int i = 0; i < 4; i++) {
            int m = ih * 64 + ty * 4 + i;
            if (m0 + m >= count) continue;
            int tok = sTok[m];
            float* orow = outdst + (size_t)tok * HIDDEN + n0;
            #pragma unroll
            for (int jh = 0; jh < 2; jh++) {
                float4 v;
                v.x = fmaxf(acc[ih * 4 + i][jh * 4 + 0] + bb[jh * 4 + 0], 0.0f);
                v.y = fmaxf(acc[ih * 4 + i][jh * 4 + 1] + bb[jh * 4 + 1], 0.0f);
                v.z = fmaxf(acc[ih * 4 + i][jh * 4 + 2] + bb[jh * 4 + 2], 0.0f);
                v.w = fmaxf(acc[ih * 4 + i][jh * 4 + 3] + bb[jh * 4 + 3], 0.0f);
                *(float4*)&orow[jh * 64 + tx * 4] = v;
            }
        }
    }
}

extern "C" void kernel_launch(void* const* d_in, const int* in_sizes, int n_in,
                              void* d_out, int out_size) {
    const float* x      = (const float*)d_in[0];
    const int*   ops    = (const int*)  d_in[1];
    const float* op_emb = (const float*)d_in[2];
    const float* W1     = (const float*)d_in[3];
    const float* b1     = (const float*)d_in[4];
    const float* W2     = (const float*)d_in[5];
    const float* b2     = (const float*)d_in[6];
    float* out = (float*)d_out;

    zero_counts_kernel<<<1, 32>>>();
    route_kernel<<<BATCH / 256, 256>>>(ops);

    dim3 grid(HIDDEN / 128, BATCH / 128, NOPS);   // (n-tiles, m-tiles, experts)
    grouped_gemm_kernel<KAUG,   true ><<<grid, 256>>>(x, op_emb, W1, b1, out);
    grouped_gemm_kernel<HIDDEN, false><<<grid, 256>>>(x, op_emb, W2, b2, out);
}

// round 4
// speedup vs baseline: 2.7747x; 2.7747x over previous
#include <cuda_runtime.h>
#include <cstdint>

#define HIDDEN 1024
#define EMBD   512
#define KAUG   1536
#define NOPS   8
#define BATCH  16384

#define BM 128
#define BN 128
#define BK 32
#define STAGES 3
#define STAGE_BYTES 32768            /* A 16KB + B 16KB */
#define OFF_TOK  (STAGES * STAGE_BYTES)
#define OFF_BIAS (OFF_TOK + 512)
#define SMEM_TOTAL (OFF_BIAS + 512)

// ---------------- device scratch ----------------
__device__ int      g_counts[NOPS];
__device__ int      g_bucket[NOPS][BATCH];
__device__ float    g_H[(size_t)BATCH * HIDDEN];              // tf32 bits, k-permuted
__device__ uint32_t g_Xc[(size_t)BATCH * HIDDEN];             // tf32(x), k-permuted
__device__ uint32_t g_Ec[NOPS * EMBD];                        // tf32(emb), k-permuted
__device__ float    g_WT1[(size_t)NOPS * HIDDEN * KAUG];      // [e][n][perm k] tf32
__device__ float    g_WT2[(size_t)NOPS * HIDDEN * HIDDEN];    // [e][n][perm k] tf32

// ---------------- helpers ----------------
__device__ __forceinline__ uint32_t smem_u32(const void* p) {
    uint32_t a;
    asm("{ .reg .u64 t; cvta.to.shared.u64 t, %1; cvt.u32.u64 %0, t; }" : "=r"(a) : "l"(p));
    return a;
}
__device__ __forceinline__ uint32_t f2tf32(float f) {
    uint32_t r; asm("cvt.rna.tf32.f32 %0, %1;" : "=r"(r) : "f"(f)); return r;
}
__device__ __forceinline__ void cp16(uint32_t dst, const void* src) {
    asm volatile("cp.async.cg.shared.global [%0], [%1], 16;" :: "r"(dst), "l"(src));
}
#define CP_COMMIT() asm volatile("cp.async.commit_group;" ::: "memory")
#define CP_WAIT1()  asm volatile("cp.async.wait_group 1;" ::: "memory")

__device__ __forceinline__ void mma_tf32_16888(
    float& c0, float& c1, float& c2, float& c3,
    uint32_t a0, uint32_t a1, uint32_t a2, uint32_t a3,
    uint32_t b0, uint32_t b1)
{
    asm volatile(
        "mma.sync.aligned.m16n8k8.row.col.f32.tf32.tf32.f32 "
        "{%0,%1,%2,%3}, {%4,%5,%6,%7}, {%8,%9}, {%0,%1,%2,%3};"
        : "+f"(c0), "+f"(c1), "+f"(c2), "+f"(c3)
        : "r"(a0), "r"(a1), "r"(a2), "r"(a3), "r"(b0), "r"(b1));
}

// permuted position of k within its 16-block: k = t + 4u -> (k & ~15) + 4t + u
__device__ __forceinline__ int pperm(int k) {
    return (k & ~15) + ((k & 3) << 2) + ((k >> 2) & 3);
}

// ---------------- routing ----------------
__global__ void zero_counts_kernel() {
    if (threadIdx.x < NOPS) g_counts[threadIdx.x] = 0;
}
__global__ void route_kernel(const int* __restrict__ ops) {
    int t = blockIdx.x * blockDim.x + threadIdx.x;
    if (t < BATCH) {
        int e = ops[t];
        int slot = atomicAdd(&g_counts[e], 1);
        g_bucket[e][slot] = t;
    }
}

// ---------------- cvt + k-permute (x, emb) ----------------
// out float4 #f holds source elements {16*(f>>2) + (f&3) + 4u : u=0..3}
__global__ void cvt_perm_kernel(const float* __restrict__ in, uint32_t* __restrict__ out, int n4) {
    int f = blockIdx.x * blockDim.x + threadIdx.x;
    if (f >= n4) return;
    const float* p = in + (f >> 2) * 16 + (f & 3);
    uint4 v;
    v.x = f2tf32(p[0]); v.y = f2tf32(p[4]); v.z = f2tf32(p[8]); v.w = f2tf32(p[12]);
    ((uint4*)out)[f] = v;
}

// ---------------- W transpose + tf32 + k-permute: WT[e][n][perm(k)] = tf32(W[e][k][n]) ----------------
__global__ void transpose_tf32_kernel(const float* __restrict__ W, float* __restrict__ WT,
                                      int K, int N) {
    __shared__ float t[32][33];
    const int e = blockIdx.z;
    const float* Wb = W + (size_t)e * K * N;
    float* WTb = WT + (size_t)e * N * K;
    const int k0 = blockIdx.y * 32, n0 = blockIdx.x * 32;
    const int x = threadIdx.x, y = threadIdx.y;   // (32, 8)
    #pragma unroll
    for (int r = 0; r < 4; r++)
        t[y + 8*r][x] = Wb[(size_t)(k0 + y + 8*r) * N + n0 + x];
    __syncthreads();
    const int px = (x & 16) + ((x & 3) << 2) + ((x >> 2) & 3);   // perm within 32
    #pragma unroll
    for (int r = 0; r < 4; r++)
        WTb[(size_t)(n0 + y + 8*r) * K + k0 + px] =
            __uint_as_float(f2tf32(t[x][y + 8*r]));
}

// ---------------- grouped tf32 GEMM via mma.sync ----------------
// out[tok, n0:n0+128] = relu( A[tok] @ WT[e]^T + b[e] )
// CTA 128x128x32, 4 warps of 64x64, 3-stage cp.async
template<int KTOT, bool IS_L1>
__global__ void __launch_bounds__(128, 2) moe_gemm_mma(
    const float* __restrict__ x_unused,
    const float* __restrict__ WT,
    const float* __restrict__ bias,
    float* __restrict__ outp)
{
    const int e = blockIdx.z;
    const int count = g_counts[e];
    const int m0 = blockIdx.y * BM;
    if (m0 >= count) return;
    const int n0 = blockIdx.x * BN;

    extern __shared__ char smem[];
    const uint32_t sb = smem_u32(smem);
    const int tid = threadIdx.x;
    const int wid = tid >> 5, lane = tid & 31;
    const int g = lane >> 2, t4 = lane & 3;
    const int wm = wid >> 1, wn = wid & 1;

    int*   sTok  = (int*)(smem + OFF_TOK);
    float* sBias = (float*)(smem + OFF_BIAS);
    {
        int idx = m0 + tid;
        sTok[tid]  = g_bucket[e][idx < count ? idx : count - 1];
        sBias[tid] = bias[e * HIDDEN + n0 + tid];
    }
    __syncthreads();

    const float* __restrict__ Asrc = IS_L1 ? (const float*)g_Xc : g_H;
    const float* __restrict__ WTe  = WT + (size_t)e * HIDDEN * KTOT;
    const uint32_t* __restrict__ Ec = g_Ec + e * EMBD;

    // ---- cp.async loader: thread -> unit u = tid&7, rows (tid>>3) + 16*i ----
    const int lu = tid & 7;
    const int lr0 = tid >> 3;
    const uint32_t lsw = (uint32_t)(lu ^ ((lr0 & 1) << 2)) << 4;  // byte offset of 16B unit in row

    auto load_chunk = [&](int chunk, int buf) {
        const int k0 = chunk * BK;
        const uint32_t Abu = sb + buf * STAGE_BYTES;
        const uint32_t Bbu = Abu + 16384;
        #pragma unroll
        for (int i = 0; i < 8; i++) {
            const int r = lr0 + i * 16;
            const float* asrc;
            if (IS_L1 && k0 >= HIDDEN)
                asrc = (const float*)(Ec + (k0 - HIDDEN));
            else
                asrc = Asrc + (size_t)sTok[r] * HIDDEN + k0;
            cp16(Abu + r * 128 + lsw, asrc + lu * 4);
            cp16(Bbu + r * 128 + lsw, WTe + (size_t)(n0 + r) * KTOT + k0 + lu * 4);
        }
    };

    float c[4][8][4];
    #pragma unroll
    for (int im = 0; im < 4; im++)
        #pragma unroll
        for (int in_ = 0; in_ < 8; in_++)
            #pragma unroll
            for (int j = 0; j < 4; j++) c[im][in_][j] = 0.0f;

    constexpr int NC = KTOT / BK;

    load_chunk(0, 0); CP_COMMIT();
    load_chunk(1, 1); CP_COMMIT();

    for (int i = 0; i < NC; i++) {
        CP_WAIT1();
        __syncthreads();
        const int nb = i + 2;
        if (nb < NC) load_chunk(nb, nb % STAGES);
        CP_COMMIT();

        const char* Ab = smem + (i % STAGES) * STAGE_BYTES;
        const char* Bb = Ab + 16384;

        #pragma unroll
        for (int kb = 0; kb < 2; kb++) {
            uint4 av0[4], av8[4], bv[8];
            #pragma unroll
            for (int im = 0; im < 4; im++) {
                const int r0 = wm * 64 + im * 16 + g;
                const int r8 = r0 + 8;
                av0[im] = *(const uint4*)(Ab + r0 * 128 + (((kb ^ (r0 & 1)) * 4 + t4) << 4));
                av8[im] = *(const uint4*)(Ab + r8 * 128 + (((kb ^ (r8 & 1)) * 4 + t4) << 4));
            }
            #pragma unroll
            for (int in_ = 0; in_ < 8; in_++) {
                const int rb = wn * 64 + in_ * 8 + g;
                bv[in_] = *(const uint4*)(Bb + rb * 128 + (((kb ^ (rb & 1)) * 4 + t4) << 4));
            }
            #pragma unroll
            for (int s2 = 0; s2 < 2; s2++) {
                #pragma unroll
                for (int im = 0; im < 4; im++) {
                    const uint32_t a0 = s2 ? av0[im].z : av0[im].x;
                    const uint32_t a2 = s2 ? av0[im].w : av0[im].y;
                    const uint32_t a1 = s2 ? av8[im].z : av8[im].x;
                    const uint32_t a3 = s2 ? av8[im].w : av8[im].y;
                    #pragma unroll
                    for (int in_ = 0; in_ < 8; in_++) {
                        const uint32_t b0 = s2 ? bv[in_].z : bv[in_].x;
                        const uint32_t b1 = s2 ? bv[in_].w : bv[in_].y;
                        mma_tf32_16888(c[im][in_][0], c[im][in_][1], c[im][in_][2], c[im][in_][3],
                                       a0, a1, a2, a3, b0, b1);
                    }
                }
            }
        }
        __syncthreads();
    }

    // ---- epilogue ----
    #pragma unroll
    for (int im = 0; im < 4; im++) {
        const int r0 = wm * 64 + im * 16 + g;
        const int r8 = r0 + 8;
        const bool v0 = (m0 + r0) < count;
        const bool v8 = (m0 + r8) < count;
        const int tok0 = sTok[r0];
        const int tok8 = sTok[r8];
        #pragma unroll
        for (int in_ = 0; in_ < 8; in_++) {
            const int cb = wn * 64 + in_ * 8 + 2 * t4;   // local col (0..127)
            const float bias0 = sBias[cb], bias1 = sBias[cb + 1];
            float y00 = fmaxf(c[im][in_][0] + bias0, 0.0f);
            float y01 = fmaxf(c[im][in_][1] + bias1, 0.0f);
            float y80 = fmaxf(c[im][in_][2] + bias0, 0.0f);
            float y81 = fmaxf(c[im][in_][3] + bias1, 0.0f);
            if (IS_L1) {
                // store H as tf32 bits at k-permuted positions
                const int p0 = pperm(n0 + cb);
                const int p1 = pperm(n0 + cb + 1);
                if (v0) {
                    float* h = g_H + (size_t)tok0 * HIDDEN;
                    h[p0] = __uint_as_float(f2tf32(y00));
                    h[p1] = __uint_as_float(f2tf32(y01));
                }
                if (v8) {
                    float* h = g_H + (size_t)tok8 * HIDDEN;
                    h[p0] = __uint_as_float(f2tf32(y80));
                    h[p1] = __uint_as_float(f2tf32(y81));
                }
            } else {
                if (v0) *(float2*)(outp + (size_t)tok0 * HIDDEN + n0 + cb) = make_float2(y00, y01);
                if (v8) *(float2*)(outp + (size_t)tok8 * HIDDEN + n0 + cb) = make_float2(y80, y81);
            }
        }
    }
}

// ---------------- launch ----------------
extern "C" void kernel_launch(void* const* d_in, const int* in_sizes, int n_in,
                              void* d_out, int out_size) {
    const float* x      = (const float*)d_in[0];
    const int*   ops    = (const int*)  d_in[1];
    const float* op_emb = (const float*)d_in[2];
    const float* W1     = (const float*)d_in[3];
    const float* b1     = (const float*)d_in[4];
    const float* W2     = (const float*)d_in[5];
    const float* b2     = (const float*)d_in[6];
    float* out = (float*)d_out;

    void *xc = nullptr, *ec = nullptr, *wt1 = nullptr, *wt2 = nullptr;
    cudaGetSymbolAddress(&xc,  g_Xc);
    cudaGetSymbolAddress(&ec,  g_Ec);
    cudaGetSymbolAddress(&wt1, g_WT1);
    cudaGetSymbolAddress(&wt2, g_WT2);

    cudaFuncSetAttribute(moe_gemm_mma<KAUG, true>,
                         cudaFuncAttributeMaxDynamicSharedMemorySize, SMEM_TOTAL);
    cudaFuncSetAttribute(moe_gemm_mma<HIDDEN, false>,
                         cudaFuncAttributeMaxDynamicSharedMemorySize, SMEM_TOTAL);

    zero_counts_kernel<<<1, 32>>>();
    route_kernel<<<BATCH / 256, 256>>>(ops);

    cvt_perm_kernel<<<(BATCH * HIDDEN / 4) / 256, 256>>>(x, (uint32_t*)xc, BATCH * HIDDEN / 4);
    cvt_perm_kernel<<<(NOPS * EMBD / 4 + 255) / 256, 256>>>(op_emb, (uint32_t*)ec, NOPS * EMBD / 4);

    transpose_tf32_kernel<<<dim3(HIDDEN/32, KAUG/32, NOPS),   dim3(32, 8)>>>(W1, (float*)wt1, KAUG, HIDDEN);
    transpose_tf32_kernel<<<dim3(HIDDEN/32, HIDDEN/32, NOPS), dim3(32, 8)>>>(W2, (float*)wt2, HIDDEN, HIDDEN);

    dim3 grid(HIDDEN / BN, BATCH / BM, NOPS);
    moe_gemm_mma<KAUG,   true ><<<grid, 128, SMEM_TOTAL>>>(x, (const float*)wt1, b1, out);
    moe_gemm_mma<HIDDEN, false><<<grid, 128, SMEM_TOTAL>>>(x, (const float*)wt2, b2, out);
}